// round 6
// baseline (speedup 1.0000x reference)
#include <cuda_runtime.h>
#include <cuda_bf16.h>
#include <mma.h>
#include <stdint.h>
#include <math.h>

using namespace nvcuda;

#define T_TOK 1024
#define H_DIM 2048
#define I_DIM 1408
#define E_NUM 8
#define LDA   40   // smem leading dim (elems), row stride 80B (16B-aligned)

typedef wmma::fragment<wmma::matrix_a, 16, 16, 16, __nv_bfloat16, wmma::row_major> FragA;
typedef wmma::fragment<wmma::matrix_b, 16, 16, 16, __nv_bfloat16, wmma::col_major> FragB;
typedef wmma::fragment<wmma::accumulator, 16, 16, 16, float> FragC;

// ---------------- device scratch ----------------
__device__ int   g_count[E_NUM];
__device__ int   g_tok[E_NUM * T_TOK];
__device__ float g_wt [E_NUM * T_TOK];
__device__ float g_hroute[(size_t)E_NUM * T_TOK * I_DIM];
__device__ float g_hshared[(size_t)T_TOK * I_DIM];

// ---------------- helpers ----------------
__device__ __forceinline__ uint32_t b2u(__nv_bfloat162 h) { return *reinterpret_cast<uint32_t*>(&h); }

// 8 fp32 -> 8 bf16 hi (uint4) + 8 bf16 lo (uint4)
__device__ __forceinline__ void cvt8(const float4 a, const float4 b, uint4& hi, uint4& lo) {
    __nv_bfloat162 h0 = __floats2bfloat162_rn(a.x, a.y);
    __nv_bfloat162 h1 = __floats2bfloat162_rn(a.z, a.w);
    __nv_bfloat162 h2 = __floats2bfloat162_rn(b.x, b.y);
    __nv_bfloat162 h3 = __floats2bfloat162_rn(b.z, b.w);
    __nv_bfloat162 l0 = __floats2bfloat162_rn(a.x - __low2float(h0), a.y - __high2float(h0));
    __nv_bfloat162 l1 = __floats2bfloat162_rn(a.z - __low2float(h1), a.w - __high2float(h1));
    __nv_bfloat162 l2 = __floats2bfloat162_rn(b.x - __low2float(h2), b.y - __high2float(h2));
    __nv_bfloat162 l3 = __floats2bfloat162_rn(b.z - __low2float(h3), b.w - __high2float(h3));
    hi = make_uint4(b2u(h0), b2u(h1), b2u(h2), b2u(h3));
    lo = make_uint4(b2u(l0), b2u(l1), b2u(l2), b2u(l3));
}
// 4 fp32 -> 4 bf16 hi (uint2) + lo (uint2)
__device__ __forceinline__ void cvt4(const float4 a, uint2& hi, uint2& lo) {
    __nv_bfloat162 h0 = __floats2bfloat162_rn(a.x, a.y);
    __nv_bfloat162 h1 = __floats2bfloat162_rn(a.z, a.w);
    __nv_bfloat162 l0 = __floats2bfloat162_rn(a.x - __low2float(h0), a.y - __high2float(h0));
    __nv_bfloat162 l1 = __floats2bfloat162_rn(a.z - __low2float(h1), a.w - __high2float(h1));
    hi = make_uint2(b2u(h0), b2u(h1));
    lo = make_uint2(b2u(l0), b2u(l1));
}

// ---------------- zero + routing ----------------
__global__ void zero_kernel(float* __restrict__ out, int n) {
    int i = blockIdx.x * blockDim.x + threadIdx.x;
    if (i < n) out[i] = 0.0f;
    if (i < E_NUM) g_count[i] = 0;
}

__global__ void routing_kernel(const float* __restrict__ x, const float* __restrict__ gw) {
    int t = blockIdx.x * blockDim.x + threadIdx.x;
    if (t >= T_TOK) return;
    float logits[E_NUM];
#pragma unroll
    for (int e = 0; e < E_NUM; e++) logits[e] = 0.0f;
    const float* xr = x + (size_t)t * H_DIM;
    for (int h = 0; h < H_DIM; h += 4) {
        float4 xv = *(const float4*)(xr + h);
#pragma unroll
        for (int e = 0; e < E_NUM; e++) {
            const float* wr = gw + (size_t)e * H_DIM + h;
            logits[e] += xv.x * wr[0] + xv.y * wr[1] + xv.z * wr[2] + xv.w * wr[3];
        }
    }
    int i0 = 0;
#pragma unroll
    for (int e = 1; e < E_NUM; e++) if (logits[e] > logits[i0]) i0 = e;
    int i1 = -1;
#pragma unroll
    for (int e = 0; e < E_NUM; e++) {
        if (e == i0) continue;
        if (i1 < 0 || logits[e] > logits[i1]) i1 = e;
    }
    float e1 = expf(logits[i1] - logits[i0]);
    float inv = 1.0f / (1.0f + e1);
    int s0 = atomicAdd(&g_count[i0], 1);
    g_tok[i0 * T_TOK + s0] = t;  g_wt[i0 * T_TOK + s0] = inv;
    int s1 = atomicAdd(&g_count[i1], 1);
    g_tok[i1 * T_TOK + s1] = t;  g_wt[i1 * T_TOK + s1] = e1 * inv;
}

// ---------------- gate+up GEMM (wmma bf16x3, fused silu) ----------------
// BM=128 BN=64 BK=32, 512 threads (16 warps 4x4), warp tile 32x16 per matrix.
// smem: Ah 10240 | Al 10240 | Gh 5120 | Gl 5120 | Uh 5120 | Ul 5120 = 40960B
#define GU_OFF_AL 10240
#define GU_OFF_GH 20480
#define GU_OFF_GL 25600
#define GU_OFF_UH 30720
#define GU_OFF_UL 35840

__global__ void __launch_bounds__(512, 1)
gu_kernel(const float* __restrict__ X, const float* __restrict__ Wg,
          const float* __restrict__ Wu, float* __restrict__ Hout, int routed) {
    __shared__ char sm[40960];
    const int e = blockIdx.z;
    const int count = routed ? g_count[e] : T_TOK;
    const int m0 = blockIdx.y * 128;
    if (m0 >= count) return;
    const int n0 = blockIdx.x * 64;

    const int tid = threadIdx.x;
    const int wid = tid >> 5;
    const int wm = wid >> 2, wn = wid & 3;

    // A loader: row = tid>>2 (128 rows), quarter = tid&3 -> 8 fp32
    const int ar = tid >> 2, aq = tid & 3;
    const int mrow = m0 + ar;
    const bool aval = mrow < count;
    int tok = 0;
    if (aval) tok = routed ? g_tok[e * T_TOK + mrow] : mrow;
    const float4* ap = (const float4*)(X + (size_t)tok * H_DIM) + aq * 2;
    // B loaders: row n = tid>>3 (64 rows), oct = tid&7 -> 4 fp32
    const int bn = tid >> 3, bo = tid & 7;
    const float4* gp = (const float4*)(Wg + (size_t)e * I_DIM * H_DIM + (size_t)(n0 + bn) * H_DIM) + bo;
    const float4* up = (const float4*)(Wu + (size_t)e * I_DIM * H_DIM + (size_t)(n0 + bn) * H_DIM) + bo;

    const uint32_t aoff = (uint32_t)(ar * LDA + aq * 8) * 2;
    const uint32_t boff = (uint32_t)(bn * LDA + bo * 4) * 2;

    FragC accg[2], accu[2];
#pragma unroll
    for (int i = 0; i < 2; i++) { wmma::fill_fragment(accg[i], 0.0f); wmma::fill_fragment(accu[i], 0.0f); }

    float4 ra0, ra1, rg, ru;
    ra0 = ap[0]; ra1 = ap[1]; rg = gp[0]; ru = up[0];

    const __nv_bfloat16* sAh = (const __nv_bfloat16*)sm;
    const __nv_bfloat16* sAl = (const __nv_bfloat16*)(sm + GU_OFF_AL);
    const __nv_bfloat16* sGh = (const __nv_bfloat16*)(sm + GU_OFF_GH);
    const __nv_bfloat16* sGl = (const __nv_bfloat16*)(sm + GU_OFF_GL);
    const __nv_bfloat16* sUh = (const __nv_bfloat16*)(sm + GU_OFF_UH);
    const __nv_bfloat16* sUl = (const __nv_bfloat16*)(sm + GU_OFF_UL);

    for (int kk = 0; kk < 64; kk++) {
        if (kk) __syncthreads();
        {   // convert + store current chunk
            uint4 hi, lo;
            cvt8(ra0, ra1, hi, lo);
            *(uint4*)(sm + aoff) = hi;
            *(uint4*)(sm + GU_OFF_AL + aoff) = lo;
            uint2 h2, l2;
            cvt4(rg, h2, l2);
            *(uint2*)(sm + GU_OFF_GH + boff) = h2;
            *(uint2*)(sm + GU_OFF_GL + boff) = l2;
            cvt4(ru, h2, l2);
            *(uint2*)(sm + GU_OFF_UH + boff) = h2;
            *(uint2*)(sm + GU_OFF_UL + boff) = l2;
        }
        __syncthreads();
        if (kk < 63) {  // prefetch next chunk
            const float4* a4 = ap + (kk + 1) * 8;
            ra0 = a4[0]; ra1 = a4[1];
            rg = gp[(kk + 1) * 8]; ru = up[(kk + 1) * 8];
        }
        // compute
#pragma unroll
        for (int ks = 0; ks < 2; ks++) {
            const int k0 = ks * 16;
            FragA ah[2], al[2];
#pragma unroll
            for (int mi = 0; mi < 2; mi++) {
                const int rbase = (wm * 32 + mi * 16) * LDA + k0;
                wmma::load_matrix_sync(ah[mi], sAh + rbase, LDA);
                wmma::load_matrix_sync(al[mi], sAl + rbase, LDA);
            }
            const int cbase = (wn * 16) * LDA + k0;
            FragB bh, bl;
            wmma::load_matrix_sync(bh, sGh + cbase, LDA);
            wmma::load_matrix_sync(bl, sGl + cbase, LDA);
#pragma unroll
            for (int mi = 0; mi < 2; mi++) {
                wmma::mma_sync(accg[mi], ah[mi], bh, accg[mi]);
                wmma::mma_sync(accg[mi], ah[mi], bl, accg[mi]);
                wmma::mma_sync(accg[mi], al[mi], bh, accg[mi]);
            }
            wmma::load_matrix_sync(bh, sUh + cbase, LDA);
            wmma::load_matrix_sync(bl, sUl + cbase, LDA);
#pragma unroll
            for (int mi = 0; mi < 2; mi++) {
                wmma::mma_sync(accu[mi], ah[mi], bh, accu[mi]);
                wmma::mma_sync(accu[mi], ah[mi], bl, accu[mi]);
                wmma::mma_sync(accu[mi], al[mi], bh, accu[mi]);
            }
        }
    }

    // epilogue: silu(g)*u, store directly to Hout (rows >= count are never read)
    const size_t rowbase = routed ? (size_t)e * T_TOK : 0;
#pragma unroll
    for (int mi = 0; mi < 2; mi++) {
#pragma unroll
        for (int i = 0; i < accg[mi].num_elements; i++) {
            float g = accg[mi].x[i];
            float u = accu[mi].x[i];
            accg[mi].x[i] = (g / (1.0f + __expf(-g))) * u;
        }
        const int m = m0 + wm * 32 + mi * 16;
        wmma::store_matrix_sync(Hout + (rowbase + m) * (size_t)I_DIM + n0 + wn * 16,
                                accg[mi], I_DIM, wmma::mem_row_major);
    }
}

// ---------------- down GEMM (wmma bf16x3, weighted atomic scatter) ----------------
// BM=128 BN=64 BK=32, K=1408 (44 chunks)
// smem tiles: Ah 10240 | Al 10240 | Bh 5120 | Bl 5120 = 30720B ; epilogue reuses as 128x68 fp32 (34816B)
#define DN_OFF_AL 10240
#define DN_OFF_BH 20480
#define DN_OFF_BL 25600
#define DN_LDO 68

__global__ void __launch_bounds__(512, 1)
dn_kernel(const float* __restrict__ Hbuf, const float* __restrict__ Wd,
          float* __restrict__ out, int routed) {
    __shared__ char sm[34816];
    const int e = blockIdx.z;
    const int count = routed ? g_count[e] : T_TOK;
    const int m0 = blockIdx.y * 128;
    if (m0 >= count) return;
    const int n0 = blockIdx.x * 64;

    const int tid = threadIdx.x;
    const int wid = tid >> 5;
    const int wm = wid >> 2, wn = wid & 3;

    const int ar = tid >> 2, aq = tid & 3;
    const int mrow = m0 + ar;
    const bool aval = mrow < count;
    const size_t rowbase = routed ? (size_t)e * T_TOK : 0;
    const float4* ap = (const float4*)(Hbuf + (rowbase + (aval ? mrow : m0)) * (size_t)I_DIM) + aq * 2;
    const int bn = tid >> 3, bo = tid & 7;
    const float4* bp = (const float4*)(Wd + (size_t)e * H_DIM * I_DIM + (size_t)(n0 + bn) * I_DIM) + bo;

    const uint32_t aoff = (uint32_t)(ar * LDA + aq * 8) * 2;
    const uint32_t boff = (uint32_t)(bn * LDA + bo * 4) * 2;

    FragC acc[2];
#pragma unroll
    for (int i = 0; i < 2; i++) wmma::fill_fragment(acc[i], 0.0f);

    float4 ra0, ra1, rb;
    ra0 = ap[0]; ra1 = ap[1]; rb = bp[0];

    const __nv_bfloat16* sAh = (const __nv_bfloat16*)sm;
    const __nv_bfloat16* sAl = (const __nv_bfloat16*)(sm + DN_OFF_AL);
    const __nv_bfloat16* sBh = (const __nv_bfloat16*)(sm + DN_OFF_BH);
    const __nv_bfloat16* sBl = (const __nv_bfloat16*)(sm + DN_OFF_BL);

    for (int kk = 0; kk < 44; kk++) {
        if (kk) __syncthreads();
        {
            uint4 hi, lo;
            cvt8(ra0, ra1, hi, lo);
            *(uint4*)(sm + aoff) = hi;
            *(uint4*)(sm + DN_OFF_AL + aoff) = lo;
            uint2 h2, l2;
            cvt4(rb, h2, l2);
            *(uint2*)(sm + DN_OFF_BH + boff) = h2;
            *(uint2*)(sm + DN_OFF_BL + boff) = l2;
        }
        __syncthreads();
        if (kk < 43) {
            const float4* a4 = ap + (kk + 1) * 8;
            ra0 = a4[0]; ra1 = a4[1];
            rb = bp[(kk + 1) * 8];
        }
#pragma unroll
        for (int ks = 0; ks < 2; ks++) {
            const int k0 = ks * 16;
            FragA ah[2], al[2];
#pragma unroll
            for (int mi = 0; mi < 2; mi++) {
                const int rbase = (wm * 32 + mi * 16) * LDA + k0;
                wmma::load_matrix_sync(ah[mi], sAh + rbase, LDA);
                wmma::load_matrix_sync(al[mi], sAl + rbase, LDA);
            }
            const int cbase = (wn * 16) * LDA + k0;
            FragB bh, bl;
            wmma::load_matrix_sync(bh, sBh + cbase, LDA);
            wmma::load_matrix_sync(bl, sBl + cbase, LDA);
#pragma unroll
            for (int mi = 0; mi < 2; mi++) {
                wmma::mma_sync(acc[mi], ah[mi], bh, acc[mi]);
                wmma::mma_sync(acc[mi], ah[mi], bl, acc[mi]);
                wmma::mma_sync(acc[mi], al[mi], bh, acc[mi]);
            }
        }
    }

    // epilogue: stage to smem, then weighted atomic scatter
    __syncthreads();
    float* sOut = (float*)sm;
#pragma unroll
    for (int mi = 0; mi < 2; mi++) {
        wmma::store_matrix_sync(sOut + (wm * 32 + mi * 16) * DN_LDO + wn * 16,
                                acc[mi], DN_LDO, wmma::mem_row_major);
    }
    __syncthreads();
    const int r = tid >> 2, c0 = (tid & 3) * 16;
    const int m = m0 + r;
    if (m < count) {
        int t; float wt;
        if (routed) { t = g_tok[e * T_TOK + m]; wt = g_wt[e * T_TOK + m]; }
        else        { t = m; wt = 1.0f; }
        float* orow = out + (size_t)t * H_DIM + n0 + c0;
        const float* srow = sOut + r * DN_LDO + c0;
#pragma unroll
        for (int j = 0; j < 16; j++) atomicAdd(&orow[j], wt * srow[j]);
    }
}

// ---------------- launch ----------------
extern "C" void kernel_launch(void* const* d_in, const int* in_sizes, int n_in,
                              void* d_out, int out_size) {
    const float* x   = (const float*)d_in[0];
    const float* gw  = (const float*)d_in[1];
    const float* egw = (const float*)d_in[2];
    const float* euw = (const float*)d_in[3];
    const float* edw = (const float*)d_in[4];
    const float* sgw = (const float*)d_in[5];
    const float* suw = (const float*)d_in[6];
    const float* sdw = (const float*)d_in[7];
    float* out = (float*)d_out;

    int n_out = T_TOK * H_DIM;
    zero_kernel<<<(n_out + 255) / 256, 256>>>(out, n_out);
    routing_kernel<<<T_TOK / 256, 256>>>(x, gw);

    gu_kernel<<<dim3(I_DIM / 64, T_TOK / 128, E_NUM), 512>>>(x, egw, euw, g_hroute, 1);
    dn_kernel<<<dim3(H_DIM / 64, T_TOK / 128, E_NUM), 512>>>(g_hroute, edw, out, 1);
    gu_kernel<<<dim3(I_DIM / 64, T_TOK / 128, 1), 512>>>(x, sgw, suw, g_hshared, 0);
    dn_kernel<<<dim3(H_DIM / 64, T_TOK / 128, 1), 512>>>(g_hshared, sdw, out, 0);
}

// round 7
// speedup vs baseline: 2.8942x; 2.8942x over previous
#include <cuda_runtime.h>
#include <cuda_bf16.h>
#include <stdint.h>
#include <math.h>

#define T_TOK 1024
#define H_DIM 2048
#define I_DIM 1408
#define E_NUM 8

#define NSTG 3
#define STG_B 65536
#define SMEM_TOT (NSTG * STG_B)

#define EGW_N (E_NUM * I_DIM * H_DIM)
#define SGW_N (I_DIM * H_DIM)
#define X_N   (T_TOK * H_DIM)
#define H_ROWS ((E_NUM + 1) * T_TOK)

// ---------------- device scratch ----------------
__device__ int   g_count[E_NUM];
__device__ int   g_tok[E_NUM * T_TOK];
__device__ float g_wt [E_NUM * T_TOK];

__device__ __align__(16) __nv_bfloat16 cx_hi[X_N],  cx_lo[X_N];
__device__ __align__(16) __nv_bfloat16 cgw_hi[EGW_N], cgw_lo[EGW_N];
__device__ __align__(16) __nv_bfloat16 cuw_hi[EGW_N], cuw_lo[EGW_N];
__device__ __align__(16) __nv_bfloat16 cdw_hi[EGW_N], cdw_lo[EGW_N];
__device__ __align__(16) __nv_bfloat16 csg_hi[SGW_N], csg_lo[SGW_N];
__device__ __align__(16) __nv_bfloat16 csu_hi[SGW_N], csu_lo[SGW_N];
__device__ __align__(16) __nv_bfloat16 csd_hi[SGW_N], csd_lo[SGW_N];
__device__ __align__(16) __nv_bfloat16 h_hi[(size_t)H_ROWS * I_DIM];
__device__ __align__(16) __nv_bfloat16 h_lo[(size_t)H_ROWS * I_DIM];

// ---------------- PTX helpers (all baseline sm_80 features) ----------------
__device__ __forceinline__ uint32_t smem_u32(const void* p) {
    uint32_t a;
    asm("{ .reg .u64 t; cvta.to.shared.u64 t, %1; cvt.u32.u64 %0, t; }" : "=r"(a) : "l"(p));
    return a;
}
__device__ __forceinline__ void cpa(uint32_t dst, const void* src) {
    asm volatile("cp.async.cg.shared.global [%0], [%1], 16;" :: "r"(dst), "l"(src));
}
#define CPA_COMMIT() asm volatile("cp.async.commit_group;" ::: "memory")
#define CPA_WAIT1()  asm volatile("cp.async.wait_group 1;" ::: "memory")

__device__ __forceinline__ void ldmx4(uint32_t* r, uint32_t a) {
    asm volatile("ldmatrix.sync.aligned.m8n8.x4.shared.b16 {%0,%1,%2,%3}, [%4];"
        : "=r"(r[0]), "=r"(r[1]), "=r"(r[2]), "=r"(r[3]) : "r"(a));
}
__device__ __forceinline__ void mma16816(float* c, const uint32_t* a, uint32_t b0, uint32_t b1) {
    asm volatile("mma.sync.aligned.m16n8k16.row.col.f32.bf16.bf16.f32 "
        "{%0,%1,%2,%3},{%4,%5,%6,%7},{%8,%9},{%0,%1,%2,%3};"
        : "+f"(c[0]), "+f"(c[1]), "+f"(c[2]), "+f"(c[3])
        : "r"(a[0]), "r"(a[1]), "r"(a[2]), "r"(a[3]), "r"(b0), "r"(b1));
}

// ---------------- small kernels ----------------
__global__ void zero_kernel(float* __restrict__ out, int n) {
    int i = blockIdx.x * blockDim.x + threadIdx.x;
    if (i < n) out[i] = 0.0f;
    if (i < E_NUM) g_count[i] = 0;
}

__global__ void routing_kernel(const float* __restrict__ x, const float* __restrict__ gw) {
    int t = blockIdx.x * blockDim.x + threadIdx.x;
    if (t >= T_TOK) return;
    float logits[E_NUM];
#pragma unroll
    for (int e = 0; e < E_NUM; e++) logits[e] = 0.0f;
    const float* xr = x + (size_t)t * H_DIM;
    for (int h = 0; h < H_DIM; h += 4) {
        float4 xv = *(const float4*)(xr + h);
#pragma unroll
        for (int e = 0; e < E_NUM; e++) {
            const float* wr = gw + (size_t)e * H_DIM + h;
            logits[e] += xv.x * wr[0] + xv.y * wr[1] + xv.z * wr[2] + xv.w * wr[3];
        }
    }
    int i0 = 0;
#pragma unroll
    for (int e = 1; e < E_NUM; e++) if (logits[e] > logits[i0]) i0 = e;
    int i1 = -1;
#pragma unroll
    for (int e = 0; e < E_NUM; e++) {
        if (e == i0) continue;
        if (i1 < 0 || logits[e] > logits[i1]) i1 = e;
    }
    float e1 = expf(logits[i1] - logits[i0]);
    float inv = 1.0f / (1.0f + e1);
    int s0 = atomicAdd(&g_count[i0], 1);
    g_tok[i0 * T_TOK + s0] = t;  g_wt[i0 * T_TOK + s0] = inv;
    int s1 = atomicAdd(&g_count[i1], 1);
    g_tok[i1 * T_TOK + s1] = t;  g_wt[i1 * T_TOK + s1] = e1 * inv;
}

__device__ __forceinline__ uint32_t b2u(__nv_bfloat162 h) { return *reinterpret_cast<uint32_t*>(&h); }

// fp32 -> bf16 hi/lo split
__global__ void cvt_kernel(const float* __restrict__ src, __nv_bfloat16* __restrict__ hi,
                           __nv_bfloat16* __restrict__ lo, int n4) {
    int i = blockIdx.x * blockDim.x + threadIdx.x;
    if (i >= n4) return;
    float4 v = *((const float4*)src + i);
    __nv_bfloat162 h0 = __floats2bfloat162_rn(v.x, v.y);
    __nv_bfloat162 h1 = __floats2bfloat162_rn(v.z, v.w);
    __nv_bfloat162 l0 = __floats2bfloat162_rn(v.x - __low2float(h0), v.y - __high2float(h0));
    __nv_bfloat162 l1 = __floats2bfloat162_rn(v.z - __low2float(h1), v.w - __high2float(h1));
    *((uint2*)hi + i) = make_uint2(b2u(h0), b2u(h1));
    *((uint2*)lo + i) = make_uint2(b2u(l0), b2u(l1));
}

// ---------------- gate+up GEMM ----------------
// BM=128, BN=64 (per matrix, gate+up both), BK=64, 256 thr (8 warps: 2m x 4n, warp tile 64x16)
// smem/stage: Ahi 16K | Alo 16K | Ghi 8K | Glo 8K | Uhi 8K | Ulo 8K = 64KB
__global__ void __launch_bounds__(256, 1) gu_kernel() {
    extern __shared__ __align__(1024) char sm[];
    const int z = blockIdx.z;
    const int count = (z < E_NUM) ? g_count[z] : T_TOK;
    const int m0 = blockIdx.y * 128;
    if (m0 >= count) return;
    const int n0 = blockIdx.x * 64;

    const int tid = threadIdx.x, lane = tid & 31, wid = tid >> 5;
    const int wm = wid & 1, wn = wid >> 1;
    const uint32_t sb = smem_u32(sm);

    // ---- loader setup: A (gathered token rows) ----
    const int lr = tid >> 1, lh = tid & 1;
    const int mrow = m0 + lr;
    int tok = (z < E_NUM) ? ((mrow < count) ? g_tok[z * T_TOK + mrow] : 0) : mrow;
    const char* sAh = (const char*)(cx_hi + (size_t)tok * H_DIM);
    const char* sAl = (const char*)(cx_lo + (size_t)tok * H_DIM);
    uint32_t dA[4];
    {
        uint32_t S = (uint32_t)(lr & 7) << 4;
#pragma unroll
        for (int uu = 0; uu < 4; uu++) {
            uint32_t unit = lh * 4 + uu;
            dA[uu] = (uint32_t)(lr * 128) + ((unit << 4) ^ S);
        }
    }
    // ---- loader setup: B (4 sub-tiles: Ghi,Glo,Uhi,Ulo) ----
    const int br = tid & 63, sel = tid >> 6;
    const __nv_bfloat16* wb;
    if (z < E_NUM) {
        size_t eo = (size_t)z * I_DIM * H_DIM;
        wb = (sel == 0) ? cgw_hi + eo : (sel == 1) ? cgw_lo + eo
           : (sel == 2) ? cuw_hi + eo : cuw_lo + eo;
    } else {
        wb = (sel == 0) ? csg_hi : (sel == 1) ? csg_lo : (sel == 2) ? csu_hi : csu_lo;
    }
    const char* sB = (const char*)(wb + (size_t)(n0 + br) * H_DIM);
    const uint32_t dBb = 32768u + (uint32_t)sel * 8192u + (uint32_t)(br * 128);
    const uint32_t SB = (uint32_t)(br & 7) << 4;

    auto load_stage = [&](int chunk, int stg) {
        uint32_t base = sb + stg * STG_B;
        int koff = chunk * 128;   // 64 elems * 2B
#pragma unroll
        for (int uu = 0; uu < 4; uu++) {
            int so = koff + (lh * 4 + uu) * 16;
            cpa(base + dA[uu], sAh + so);
            cpa(base + 16384 + dA[uu], sAl + so);
        }
#pragma unroll
        for (int uu = 0; uu < 8; uu++)
            cpa(base + dBb + (((uint32_t)uu << 4) ^ SB), sB + koff + uu * 16);
    };

    // ---- compute lane constants ----
    const int ra = wm * 64 + (((lane >> 3) & 1) << 3) + (lane & 7);
    const uint32_t Sa = (uint32_t)(ra & 7) << 4;
    const int rbn = wn * 16 + (((lane >> 3) & 1) << 3) + (lane & 7);
    const uint32_t Sbn = (uint32_t)(rbn & 7) << 4;
    const uint32_t g2 = (uint32_t)(lane >> 4) << 4;

    float acc[2][4][2][4];
#pragma unroll
    for (int a = 0; a < 2; a++)
#pragma unroll
        for (int b = 0; b < 4; b++)
#pragma unroll
            for (int c = 0; c < 2; c++)
#pragma unroll
                for (int d = 0; d < 4; d++) acc[a][b][c][d] = 0.0f;

    load_stage(0, 0); CPA_COMMIT();
    load_stage(1, 1); CPA_COMMIT();

    const int NC = H_DIM / 64;  // 32
    for (int c = 0; c < NC; c++) {
        CPA_WAIT1();
        __syncthreads();
        if (c + 2 < NC) load_stage(c + 2, (c + 2) % NSTG);
        CPA_COMMIT();
        uint32_t base = sb + (c % NSTG) * STG_B;
#pragma unroll
        for (int ks = 0; ks < 4; ks++) {
            uint32_t kx = ((uint32_t)ks << 5) | g2;
            uint32_t Ah[4][4], Al[4][4];
#pragma unroll
            for (int mf = 0; mf < 4; mf++) {
                uint32_t ro = (uint32_t)((ra + mf * 16) * 128);
                ldmx4(Ah[mf], base + ro + (kx ^ Sa));
                ldmx4(Al[mf], base + 16384 + ro + (kx ^ Sa));
            }
#pragma unroll
            for (int mat = 0; mat < 2; mat++) {
                uint32_t bh[4], bl[4];
                uint32_t bo = base + 32768 + (uint32_t)mat * 16384 + (uint32_t)(rbn * 128) + (kx ^ Sbn);
                ldmx4(bh, bo);
                ldmx4(bl, bo + 8192);
#pragma unroll
                for (int mf = 0; mf < 4; mf++) {
#pragma unroll
                    for (int nf = 0; nf < 2; nf++) {
                        mma16816(acc[mat][mf][nf], Ah[mf], bh[nf], bh[nf + 2]);
                        mma16816(acc[mat][mf][nf], Ah[mf], bl[nf], bl[nf + 2]);
                        mma16816(acc[mat][mf][nf], Al[mf], bh[nf], bh[nf + 2]);
                    }
                }
            }
        }
    }

    // ---- epilogue: silu(g)*u -> h hi/lo (bf16) ----
    const size_t rowbase = (z < E_NUM) ? (size_t)z * T_TOK : (size_t)E_NUM * T_TOK;
#pragma unroll
    for (int mf = 0; mf < 4; mf++) {
        int R0 = m0 + wm * 64 + mf * 16 + (lane >> 2);
#pragma unroll
        for (int nf = 0; nf < 2; nf++) {
            int C = n0 + wn * 16 + nf * 8 + (lane & 3) * 2;
            float* gf = acc[0][mf][nf];
            float* uf = acc[1][mf][nf];
#pragma unroll
            for (int hr = 0; hr < 2; hr++) {
                int R = R0 + hr * 8;
                if (R < count) {
                    float ga = gf[hr * 2], gb = gf[hr * 2 + 1];
                    float ua = uf[hr * 2], ub = uf[hr * 2 + 1];
                    float ha = ga / (1.0f + __expf(-ga)) * ua;
                    float hb = gb / (1.0f + __expf(-gb)) * ub;
                    __nv_bfloat162 hi = __floats2bfloat162_rn(ha, hb);
                    __nv_bfloat162 lo = __floats2bfloat162_rn(ha - __low2float(hi), hb - __high2float(hi));
                    size_t off = (rowbase + R) * (size_t)I_DIM + C;
                    *(__nv_bfloat162*)(h_hi + off) = hi;
                    *(__nv_bfloat162*)(h_lo + off) = lo;
                }
            }
        }
    }
}

// ---------------- down GEMM ----------------
// BM=128, BN=128, BK=64, 256 thr (8 warps: 2m x 4n, warp tile 64x32)
// smem/stage: Ahi 16K | Alo 16K | Bhi 16K | Blo 16K = 64KB
__global__ void __launch_bounds__(256, 1) dn_kernel(float* __restrict__ out) {
    extern __shared__ __align__(1024) char sm[];
    const int z = blockIdx.z;
    const int count = (z < E_NUM) ? g_count[z] : T_TOK;
    const int m0 = blockIdx.y * 128;
    if (m0 >= count) return;
    const int n0 = blockIdx.x * 128;

    const int tid = threadIdx.x, lane = tid & 31, wid = tid >> 5;
    const int wm = wid & 1, wn = wid >> 1;
    const uint32_t sb = smem_u32(sm);
    const size_t rowbase = (z < E_NUM) ? (size_t)z * T_TOK : (size_t)E_NUM * T_TOK;

    // ---- loaders ----
    const int lr = tid >> 1, lh = tid & 1;
    const char* sAh = (const char*)(h_hi + (rowbase + m0 + lr) * (size_t)I_DIM);
    const char* sAl = (const char*)(h_lo + (rowbase + m0 + lr) * (size_t)I_DIM);
    uint32_t dA[4];
    {
        uint32_t S = (uint32_t)(lr & 7) << 4;
#pragma unroll
        for (int uu = 0; uu < 4; uu++) {
            uint32_t unit = lh * 4 + uu;
            dA[uu] = (uint32_t)(lr * 128) + ((unit << 4) ^ S);
        }
    }
    const int rB = tid >> 1, selB = tid & 1;
    const __nv_bfloat16* wd;
    if (z < E_NUM) {
        size_t eo = (size_t)z * H_DIM * I_DIM;
        wd = selB ? cdw_lo + eo : cdw_hi + eo;
    } else {
        wd = selB ? csd_lo : csd_hi;
    }
    const char* sB = (const char*)(wd + (size_t)(n0 + rB) * I_DIM);
    const uint32_t dBb = 32768u + (uint32_t)selB * 16384u + (uint32_t)(rB * 128);
    const uint32_t SB = (uint32_t)(rB & 7) << 4;

    auto load_stage = [&](int chunk, int stg) {
        uint32_t base = sb + stg * STG_B;
        int koff = chunk * 128;
#pragma unroll
        for (int uu = 0; uu < 4; uu++) {
            int so = koff + (lh * 4 + uu) * 16;
            cpa(base + dA[uu], sAh + so);
            cpa(base + 16384 + dA[uu], sAl + so);
        }
#pragma unroll
        for (int uu = 0; uu < 8; uu++)
            cpa(base + dBb + (((uint32_t)uu << 4) ^ SB), sB + koff + uu * 16);
    };

    const int ra = wm * 64 + (((lane >> 3) & 1) << 3) + (lane & 7);
    const uint32_t Sa = (uint32_t)(ra & 7) << 4;
    const int rb0 = wn * 32 + (((lane >> 3) & 1) << 3) + (lane & 7);
    const int rb1 = rb0 + 16;
    const uint32_t Sb0 = (uint32_t)(rb0 & 7) << 4;
    const uint32_t Sb1 = (uint32_t)(rb1 & 7) << 4;
    const uint32_t g2 = (uint32_t)(lane >> 4) << 4;

    float acc[4][4][4];
#pragma unroll
    for (int a = 0; a < 4; a++)
#pragma unroll
        for (int b = 0; b < 4; b++)
#pragma unroll
            for (int c = 0; c < 4; c++) acc[a][b][c] = 0.0f;

    load_stage(0, 0); CPA_COMMIT();
    load_stage(1, 1); CPA_COMMIT();

    const int NC = I_DIM / 64;  // 22
    for (int c = 0; c < NC; c++) {
        CPA_WAIT1();
        __syncthreads();
        if (c + 2 < NC) load_stage(c + 2, (c + 2) % NSTG);
        CPA_COMMIT();
        uint32_t base = sb + (c % NSTG) * STG_B;
#pragma unroll
        for (int ks = 0; ks < 4; ks++) {
            uint32_t kx = ((uint32_t)ks << 5) | g2;
            uint32_t Ah[4][4], Al[4][4];
#pragma unroll
            for (int mf = 0; mf < 4; mf++) {
                uint32_t ro = (uint32_t)((ra + mf * 16) * 128);
                ldmx4(Ah[mf], base + ro + (kx ^ Sa));
                ldmx4(Al[mf], base + 16384 + ro + (kx ^ Sa));
            }
#pragma unroll
            for (int nb = 0; nb < 2; nb++) {
                uint32_t bh[4], bl[4];
                uint32_t ro = (uint32_t)((nb ? rb1 : rb0) * 128);
                uint32_t Sx = nb ? Sb1 : Sb0;
                ldmx4(bh, base + 32768 + ro + (kx ^ Sx));
                ldmx4(bl, base + 49152 + ro + (kx ^ Sx));
#pragma unroll
                for (int mf = 0; mf < 4; mf++) {
#pragma unroll
                    for (int nf = 0; nf < 2; nf++) {
                        mma16816(acc[mf][nb * 2 + nf], Ah[mf], bh[nf], bh[nf + 2]);
                        mma16816(acc[mf][nb * 2 + nf], Ah[mf], bl[nf], bl[nf + 2]);
                        mma16816(acc[mf][nb * 2 + nf], Al[mf], bh[nf], bh[nf + 2]);
                    }
                }
            }
        }
    }

    // ---- epilogue: weighted atomic scatter ----
#pragma unroll
    for (int mf = 0; mf < 4; mf++) {
        int R0 = m0 + wm * 64 + mf * 16 + (lane >> 2);
#pragma unroll
        for (int hr = 0; hr < 2; hr++) {
            int R = R0 + hr * 8;
            if (R < count) {
                int t; float wt;
                if (z < E_NUM) { t = g_tok[z * T_TOK + R]; wt = g_wt[z * T_TOK + R]; }
                else           { t = R; wt = 1.0f; }
                float* orow = out + (size_t)t * H_DIM;
#pragma unroll
                for (int nf = 0; nf < 4; nf++) {
                    int C = n0 + wn * 32 + nf * 8 + (lane & 3) * 2;
                    atomicAdd(&orow[C],     wt * acc[mf][nf][hr * 2]);
                    atomicAdd(&orow[C + 1], wt * acc[mf][nf][hr * 2 + 1]);
                }
            }
        }
    }
}

// ---------------- launch ----------------
extern "C" void kernel_launch(void* const* d_in, const int* in_sizes, int n_in,
                              void* d_out, int out_size) {
    const float* x   = (const float*)d_in[0];
    const float* gw  = (const float*)d_in[1];
    const float* egw = (const float*)d_in[2];
    const float* euw = (const float*)d_in[3];
    const float* edw = (const float*)d_in[4];
    const float* sgw = (const float*)d_in[5];
    const float* suw = (const float*)d_in[6];
    const float* sdw = (const float*)d_in[7];
    float* out = (float*)d_out;

    cudaFuncSetAttribute(gu_kernel, cudaFuncAttributeMaxDynamicSharedMemorySize, SMEM_TOT);
    cudaFuncSetAttribute(dn_kernel, cudaFuncAttributeMaxDynamicSharedMemorySize, SMEM_TOT);

    int n_out = T_TOK * H_DIM;
    zero_kernel<<<(n_out + 255) / 256, 256>>>(out, n_out);
    routing_kernel<<<T_TOK / 256, 256>>>(x, gw);

    __nv_bfloat16 *p_cx_hi, *p_cx_lo, *p_cgw_hi, *p_cgw_lo, *p_cuw_hi, *p_cuw_lo;
    __nv_bfloat16 *p_cdw_hi, *p_cdw_lo, *p_csg_hi, *p_csg_lo, *p_csu_hi, *p_csu_lo, *p_csd_hi, *p_csd_lo;
    cudaGetSymbolAddress((void**)&p_cx_hi, cx_hi);   cudaGetSymbolAddress((void**)&p_cx_lo, cx_lo);
    cudaGetSymbolAddress((void**)&p_cgw_hi, cgw_hi); cudaGetSymbolAddress((void**)&p_cgw_lo, cgw_lo);
    cudaGetSymbolAddress((void**)&p_cuw_hi, cuw_hi); cudaGetSymbolAddress((void**)&p_cuw_lo, cuw_lo);
    cudaGetSymbolAddress((void**)&p_cdw_hi, cdw_hi); cudaGetSymbolAddress((void**)&p_cdw_lo, cdw_lo);
    cudaGetSymbolAddress((void**)&p_csg_hi, csg_hi); cudaGetSymbolAddress((void**)&p_csg_lo, csg_lo);
    cudaGetSymbolAddress((void**)&p_csu_hi, csu_hi); cudaGetSymbolAddress((void**)&p_csu_lo, csu_lo);
    cudaGetSymbolAddress((void**)&p_csd_hi, csd_hi); cudaGetSymbolAddress((void**)&p_csd_lo, csd_lo);

    cvt_kernel<<<(X_N / 4 + 255) / 256, 256>>>(x, p_cx_hi, p_cx_lo, X_N / 4);
    cvt_kernel<<<(EGW_N / 4 + 255) / 256, 256>>>(egw, p_cgw_hi, p_cgw_lo, EGW_N / 4);
    cvt_kernel<<<(EGW_N / 4 + 255) / 256, 256>>>(euw, p_cuw_hi, p_cuw_lo, EGW_N / 4);
    cvt_kernel<<<(EGW_N / 4 + 255) / 256, 256>>>(edw, p_cdw_hi, p_cdw_lo, EGW_N / 4);
    cvt_kernel<<<(SGW_N / 4 + 255) / 256, 256>>>(sgw, p_csg_hi, p_csg_lo, SGW_N / 4);
    cvt_kernel<<<(SGW_N / 4 + 255) / 256, 256>>>(suw, p_csu_hi, p_csu_lo, SGW_N / 4);
    cvt_kernel<<<(SGW_N / 4 + 255) / 256, 256>>>(sdw, p_csd_hi, p_csd_lo, SGW_N / 4);

    gu_kernel<<<dim3(I_DIM / 64, T_TOK / 128, E_NUM + 1), 256, SMEM_TOT>>>();
    dn_kernel<<<dim3(H_DIM / 128, T_TOK / 128, E_NUM + 1), 256, SMEM_TOT>>>(out);
}

// round 8
// speedup vs baseline: 3.4733x; 1.2001x over previous
#include <cuda_runtime.h>
#include <cuda_bf16.h>
#include <stdint.h>
#include <math.h>

#define T_TOK 1024
#define H_DIM 2048
#define I_DIM 1408
#define E_NUM 8

#define NSTG 3
#define STG_B 65536
#define SMEM_TOT (NSTG * STG_B)

#define EGW_N (E_NUM * I_DIM * H_DIM)
#define SGW_N (I_DIM * H_DIM)
#define X_N   (T_TOK * H_DIM)
#define H_ROWS ((E_NUM + 1) * T_TOK)

// ---------------- device scratch ----------------
__device__ int   g_count[E_NUM];
__device__ int   g_tok[E_NUM * T_TOK];
__device__ float g_wt [E_NUM * T_TOK];

__device__ __align__(16) __nv_bfloat16 cx_hi[X_N],  cx_lo[X_N];
__device__ __align__(16) __nv_bfloat16 cgw_hi[EGW_N], cgw_lo[EGW_N];
__device__ __align__(16) __nv_bfloat16 cuw_hi[EGW_N], cuw_lo[EGW_N];
__device__ __align__(16) __nv_bfloat16 cdw_hi[EGW_N], cdw_lo[EGW_N];
__device__ __align__(16) __nv_bfloat16 csg_hi[SGW_N], csg_lo[SGW_N];
__device__ __align__(16) __nv_bfloat16 csu_hi[SGW_N], csu_lo[SGW_N];
__device__ __align__(16) __nv_bfloat16 csd_hi[SGW_N], csd_lo[SGW_N];
__device__ __align__(16) __nv_bfloat16 h_hi[(size_t)H_ROWS * I_DIM];
__device__ __align__(16) __nv_bfloat16 h_lo[(size_t)H_ROWS * I_DIM];

// ---------------- PTX helpers ----------------
__device__ __forceinline__ uint32_t smem_u32(const void* p) {
    uint32_t a;
    asm("{ .reg .u64 t; cvta.to.shared.u64 t, %1; cvt.u32.u64 %0, t; }" : "=r"(a) : "l"(p));
    return a;
}
__device__ __forceinline__ void cpa(uint32_t dst, const void* src) {
    asm volatile("cp.async.cg.shared.global [%0], [%1], 16;" :: "r"(dst), "l"(src));
}
#define CPA_COMMIT() asm volatile("cp.async.commit_group;" ::: "memory")
#define CPA_WAIT1()  asm volatile("cp.async.wait_group 1;" ::: "memory")

__device__ __forceinline__ void ldmx4(uint32_t* r, uint32_t a) {
    asm volatile("ldmatrix.sync.aligned.m8n8.x4.shared.b16 {%0,%1,%2,%3}, [%4];"
        : "=r"(r[0]), "=r"(r[1]), "=r"(r[2]), "=r"(r[3]) : "r"(a));
}
__device__ __forceinline__ void mma16816(float* c, const uint32_t* a, uint32_t b0, uint32_t b1) {
    asm volatile("mma.sync.aligned.m16n8k16.row.col.f32.bf16.bf16.f32 "
        "{%0,%1,%2,%3},{%4,%5,%6,%7},{%8,%9},{%0,%1,%2,%3};"
        : "+f"(c[0]), "+f"(c[1]), "+f"(c[2]), "+f"(c[3])
        : "r"(a[0]), "r"(a[1]), "r"(a[2]), "r"(a[3]), "r"(b0), "r"(b1));
}

// ---------------- small kernels ----------------
__global__ void zero_kernel(float* __restrict__ out, int n) {
    int i = blockIdx.x * blockDim.x + threadIdx.x;
    if (i < n) out[i] = 0.0f;
    if (i < E_NUM) g_count[i] = 0;
}

__global__ void routing_kernel(const float* __restrict__ x, const float* __restrict__ gw) {
    int t = blockIdx.x * blockDim.x + threadIdx.x;
    if (t >= T_TOK) return;
    float logits[E_NUM];
#pragma unroll
    for (int e = 0; e < E_NUM; e++) logits[e] = 0.0f;
    const float* xr = x + (size_t)t * H_DIM;
    for (int h = 0; h < H_DIM; h += 4) {
        float4 xv = *(const float4*)(xr + h);
#pragma unroll
        for (int e = 0; e < E_NUM; e++) {
            const float* wr = gw + (size_t)e * H_DIM + h;
            logits[e] += xv.x * wr[0] + xv.y * wr[1] + xv.z * wr[2] + xv.w * wr[3];
        }
    }
    int i0 = 0;
#pragma unroll
    for (int e = 1; e < E_NUM; e++) if (logits[e] > logits[i0]) i0 = e;
    int i1 = -1;
#pragma unroll
    for (int e = 0; e < E_NUM; e++) {
        if (e == i0) continue;
        if (i1 < 0 || logits[e] > logits[i1]) i1 = e;
    }
    float e1 = expf(logits[i1] - logits[i0]);
    float inv = 1.0f / (1.0f + e1);
    int s0 = atomicAdd(&g_count[i0], 1);
    g_tok[i0 * T_TOK + s0] = t;  g_wt[i0 * T_TOK + s0] = inv;
    int s1 = atomicAdd(&g_count[i1], 1);
    g_tok[i1 * T_TOK + s1] = t;  g_wt[i1 * T_TOK + s1] = e1 * inv;
}

__device__ __forceinline__ uint32_t b2u(__nv_bfloat162 h) { return *reinterpret_cast<uint32_t*>(&h); }

__global__ void cvt_kernel(const float* __restrict__ src, __nv_bfloat16* __restrict__ hi,
                           __nv_bfloat16* __restrict__ lo, int n4) {
    int i = blockIdx.x * blockDim.x + threadIdx.x;
    if (i >= n4) return;
    float4 v = *((const float4*)src + i);
    __nv_bfloat162 h0 = __floats2bfloat162_rn(v.x, v.y);
    __nv_bfloat162 h1 = __floats2bfloat162_rn(v.z, v.w);
    __nv_bfloat162 l0 = __floats2bfloat162_rn(v.x - __low2float(h0), v.y - __high2float(h0));
    __nv_bfloat162 l1 = __floats2bfloat162_rn(v.z - __low2float(h1), v.w - __high2float(h1));
    *((uint2*)hi + i) = make_uint2(b2u(h0), b2u(h1));
    *((uint2*)lo + i) = make_uint2(b2u(l0), b2u(l1));
}

// ---------------- gate+up GEMM ----------------
// BM=128, BN=64 per matrix (gate & up), BK=64, 512 thr = 16 warps (4m x 4n),
// warp tile 32x16 per matrix. smem/stage: Ahi 16K | Alo 16K | Ghi 8K | Glo 8K | Uhi 8K | Ulo 8K
__global__ void __launch_bounds__(512, 1) gu_kernel() {
    extern __shared__ __align__(1024) char sm[];
    const int z = blockIdx.z;
    const int count = (z < E_NUM) ? g_count[z] : T_TOK;
    const int m0 = blockIdx.y * 128;
    if (m0 >= count) return;
    const int n0 = blockIdx.x * 64;

    const int tid = threadIdx.x, lane = tid & 31, wid = tid >> 5;
    const int wm = wid & 3, wn = wid >> 2;
    const uint32_t sb = smem_u32(sm);

    // ---- loader: A (gathered) — 128 rows, 4 thr/row, 2 units each (hi & lo) ----
    const int lr = tid >> 2, lj = (tid & 3) * 2;
    const int mrow = m0 + lr;
    int tok = (z < E_NUM) ? ((mrow < count) ? g_tok[z * T_TOK + mrow] : 0) : mrow;
    const char* sAh = (const char*)(cx_hi + (size_t)tok * H_DIM);
    const char* sAl = (const char*)(cx_lo + (size_t)tok * H_DIM);
    uint32_t dA[2];
    {
        uint32_t S = (uint32_t)(lr & 7) << 4;
#pragma unroll
        for (int uu = 0; uu < 2; uu++)
            dA[uu] = (uint32_t)(lr * 128) + ((((uint32_t)(lj + uu)) << 4) ^ S);
    }
    // ---- loader: B — sel = buffer (Gh,Gl,Uh,Ul), 64 rows, 2 thr/row, 4 units ----
    const int sel = tid >> 7, br = (tid & 127) >> 1, bh2 = tid & 1;
    const __nv_bfloat16* wb;
    if (z < E_NUM) {
        size_t eo = (size_t)z * I_DIM * H_DIM;
        wb = (sel == 0) ? cgw_hi + eo : (sel == 1) ? cgw_lo + eo
           : (sel == 2) ? cuw_hi + eo : cuw_lo + eo;
    } else {
        wb = (sel == 0) ? csg_hi : (sel == 1) ? csg_lo : (sel == 2) ? csu_hi : csu_lo;
    }
    const char* sB = (const char*)(wb + (size_t)(n0 + br) * H_DIM);
    const uint32_t dBb = 32768u + (uint32_t)sel * 8192u + (uint32_t)(br * 128);
    const uint32_t SB = (uint32_t)(br & 7) << 4;

    auto load_stage = [&](int chunk, int stg) {
        uint32_t base = sb + stg * STG_B;
        int koff = chunk * 128;
#pragma unroll
        for (int uu = 0; uu < 2; uu++) {
            int so = koff + (lj + uu) * 16;
            cpa(base + dA[uu], sAh + so);
            cpa(base + 16384 + dA[uu], sAl + so);
        }
#pragma unroll
        for (int uu = 0; uu < 4; uu++) {
            uint32_t unit = (uint32_t)(bh2 * 4 + uu);
            cpa(base + dBb + ((unit << 4) ^ SB), sB + koff + unit * 16);
        }
    };

    const int ra = wm * 32 + (((lane >> 3) & 1) << 3) + (lane & 7);
    const uint32_t Sa = (uint32_t)(ra & 7) << 4;
    const int rbn = wn * 16 + (((lane >> 3) & 1) << 3) + (lane & 7);
    const uint32_t Sbn = (uint32_t)(rbn & 7) << 4;
    const uint32_t g2 = (uint32_t)(lane >> 4) << 4;

    float acc[2][2][2][4];   // [mat][mf][nf][4]
#pragma unroll
    for (int a = 0; a < 2; a++)
#pragma unroll
        for (int b = 0; b < 2; b++)
#pragma unroll
            for (int c = 0; c < 2; c++)
#pragma unroll
                for (int d = 0; d < 4; d++) acc[a][b][c][d] = 0.0f;

    load_stage(0, 0); CPA_COMMIT();
    load_stage(1, 1); CPA_COMMIT();

    const int NC = H_DIM / 64;  // 32
    for (int c = 0; c < NC; c++) {
        CPA_WAIT1();
        __syncthreads();
        if (c + 2 < NC) load_stage(c + 2, (c + 2) % NSTG);
        CPA_COMMIT();
        uint32_t base = sb + (c % NSTG) * STG_B;
#pragma unroll
        for (int ks = 0; ks < 4; ks++) {
            uint32_t kx = ((uint32_t)ks << 5) | g2;
            uint32_t Ah[2][4], Al[2][4];
#pragma unroll
            for (int mf = 0; mf < 2; mf++) {
                uint32_t ro = (uint32_t)((ra + mf * 16) * 128);
                ldmx4(Ah[mf], base + ro + (kx ^ Sa));
                ldmx4(Al[mf], base + 16384 + ro + (kx ^ Sa));
            }
#pragma unroll
            for (int mat = 0; mat < 2; mat++) {
                uint32_t bh[4], bl[4];
                uint32_t bo = base + 32768 + (uint32_t)mat * 16384 + (uint32_t)(rbn * 128) + (kx ^ Sbn);
                ldmx4(bh, bo);
                ldmx4(bl, bo + 8192);
#pragma unroll
                for (int mf = 0; mf < 2; mf++) {
#pragma unroll
                    for (int nf = 0; nf < 2; nf++) {
                        mma16816(acc[mat][mf][nf], Ah[mf], bh[nf], bh[nf + 2]);
                        mma16816(acc[mat][mf][nf], Ah[mf], bl[nf], bl[nf + 2]);
                        mma16816(acc[mat][mf][nf], Al[mf], bh[nf], bh[nf + 2]);
                    }
                }
            }
        }
    }

    // ---- epilogue: silu(g)*u -> h hi/lo ----
    const size_t rowbase = (z < E_NUM) ? (size_t)z * T_TOK : (size_t)E_NUM * T_TOK;
#pragma unroll
    for (int mf = 0; mf < 2; mf++) {
        int R0 = m0 + wm * 32 + mf * 16 + (lane >> 2);
#pragma unroll
        for (int nf = 0; nf < 2; nf++) {
            int C = n0 + wn * 16 + nf * 8 + (lane & 3) * 2;
            float* gf = acc[0][mf][nf];
            float* uf = acc[1][mf][nf];
#pragma unroll
            for (int hr = 0; hr < 2; hr++) {
                int R = R0 + hr * 8;
                if (R < count) {
                    float ga = gf[hr * 2], gb = gf[hr * 2 + 1];
                    float ua = uf[hr * 2], ub = uf[hr * 2 + 1];
                    float ha = ga / (1.0f + __expf(-ga)) * ua;
                    float hb = gb / (1.0f + __expf(-gb)) * ub;
                    __nv_bfloat162 hi = __floats2bfloat162_rn(ha, hb);
                    __nv_bfloat162 lo = __floats2bfloat162_rn(ha - __low2float(hi), hb - __high2float(hi));
                    size_t off = (rowbase + R) * (size_t)I_DIM + C;
                    *(__nv_bfloat162*)(h_hi + off) = hi;
                    *(__nv_bfloat162*)(h_lo + off) = lo;
                }
            }
        }
    }
}

// ---------------- down GEMM ----------------
// BM=128, BN=128, BK=64, 512 thr = 16 warps (4m x 4n), warp tile 32x32
__global__ void __launch_bounds__(512, 1) dn_kernel(float* __restrict__ out) {
    extern __shared__ __align__(1024) char sm[];
    const int z = blockIdx.z;
    const int count = (z < E_NUM) ? g_count[z] : T_TOK;
    const int m0 = blockIdx.y * 128;
    if (m0 >= count) return;
    const int n0 = blockIdx.x * 128;

    const int tid = threadIdx.x, lane = tid & 31, wid = tid >> 5;
    const int wm = wid & 3, wn = wid >> 2;
    const uint32_t sb = smem_u32(sm);
    const size_t rowbase = (z < E_NUM) ? (size_t)z * T_TOK : (size_t)E_NUM * T_TOK;

    // ---- loaders ----
    const int lr = tid >> 2, lj = (tid & 3) * 2;
    const char* sAh = (const char*)(h_hi + (rowbase + m0 + lr) * (size_t)I_DIM);
    const char* sAl = (const char*)(h_lo + (rowbase + m0 + lr) * (size_t)I_DIM);
    uint32_t dA[2];
    {
        uint32_t S = (uint32_t)(lr & 7) << 4;
#pragma unroll
        for (int uu = 0; uu < 2; uu++)
            dA[uu] = (uint32_t)(lr * 128) + ((((uint32_t)(lj + uu)) << 4) ^ S);
    }
    const int selB = tid >> 8, rB = (tid & 255) >> 1, bh2 = tid & 1;
    const __nv_bfloat16* wd;
    if (z < E_NUM) {
        size_t eo = (size_t)z * H_DIM * I_DIM;
        wd = selB ? cdw_lo + eo : cdw_hi + eo;
    } else {
        wd = selB ? csd_lo : csd_hi;
    }
    const char* sB = (const char*)(wd + (size_t)(n0 + rB) * I_DIM);
    const uint32_t dBb = 32768u + (uint32_t)selB * 16384u + (uint32_t)(rB * 128);
    const uint32_t SB = (uint32_t)(rB & 7) << 4;

    auto load_stage = [&](int chunk, int stg) {
        uint32_t base = sb + stg * STG_B;
        int koff = chunk * 128;
#pragma unroll
        for (int uu = 0; uu < 2; uu++) {
            int so = koff + (lj + uu) * 16;
            cpa(base + dA[uu], sAh + so);
            cpa(base + 16384 + dA[uu], sAl + so);
        }
#pragma unroll
        for (int uu = 0; uu < 4; uu++) {
            uint32_t unit = (uint32_t)(bh2 * 4 + uu);
            cpa(base + dBb + ((unit << 4) ^ SB), sB + koff + unit * 16);
        }
    };

    const int ra = wm * 32 + (((lane >> 3) & 1) << 3) + (lane & 7);
    const uint32_t Sa = (uint32_t)(ra & 7) << 4;
    const int rb0 = wn * 32 + (((lane >> 3) & 1) << 3) + (lane & 7);
    const int rb1 = rb0 + 16;
    const uint32_t Sb0 = (uint32_t)(rb0 & 7) << 4;
    const uint32_t Sb1 = (uint32_t)(rb1 & 7) << 4;
    const uint32_t g2 = (uint32_t)(lane >> 4) << 4;

    float acc[2][4][4];   // [mf][nb*2+nf][4]
#pragma unroll
    for (int a = 0; a < 2; a++)
#pragma unroll
        for (int b = 0; b < 4; b++)
#pragma unroll
            for (int c = 0; c < 4; c++) acc[a][b][c] = 0.0f;

    load_stage(0, 0); CPA_COMMIT();
    load_stage(1, 1); CPA_COMMIT();

    const int NC = I_DIM / 64;  // 22
    for (int c = 0; c < NC; c++) {
        CPA_WAIT1();
        __syncthreads();
        if (c + 2 < NC) load_stage(c + 2, (c + 2) % NSTG);
        CPA_COMMIT();
        uint32_t base = sb + (c % NSTG) * STG_B;
#pragma unroll
        for (int ks = 0; ks < 4; ks++) {
            uint32_t kx = ((uint32_t)ks << 5) | g2;
            uint32_t Ah[2][4], Al[2][4];
#pragma unroll
            for (int mf = 0; mf < 2; mf++) {
                uint32_t ro = (uint32_t)((ra + mf * 16) * 128);
                ldmx4(Ah[mf], base + ro + (kx ^ Sa));
                ldmx4(Al[mf], base + 16384 + ro + (kx ^ Sa));
            }
#pragma unroll
            for (int nb = 0; nb < 2; nb++) {
                uint32_t bh[4], bl[4];
                uint32_t ro = (uint32_t)((nb ? rb1 : rb0) * 128);
                uint32_t Sx = nb ? Sb1 : Sb0;
                ldmx4(bh, base + 32768 + ro + (kx ^ Sx));
                ldmx4(bl, base + 49152 + ro + (kx ^ Sx));
#pragma unroll
                for (int mf = 0; mf < 2; mf++) {
#pragma unroll
                    for (int nf = 0; nf < 2; nf++) {
                        mma16816(acc[mf][nb * 2 + nf], Ah[mf], bh[nf], bh[nf + 2]);
                        mma16816(acc[mf][nb * 2 + nf], Ah[mf], bl[nf], bl[nf + 2]);
                        mma16816(acc[mf][nb * 2 + nf], Al[mf], bh[nf], bh[nf + 2]);
                    }
                }
            }
        }
    }

    // ---- epilogue: weighted atomic scatter ----
#pragma unroll
    for (int mf = 0; mf < 2; mf++) {
        int R0 = m0 + wm * 32 + mf * 16 + (lane >> 2);
#pragma unroll
        for (int hr = 0; hr < 2; hr++) {
            int R = R0 + hr * 8;
            if (R < count) {
                int t; float wt;
                if (z < E_NUM) { t = g_tok[z * T_TOK + R]; wt = g_wt[z * T_TOK + R]; }
                else           { t = R; wt = 1.0f; }
                float* orow = out + (size_t)t * H_DIM;
#pragma unroll
                for (int q = 0; q < 4; q++) {
                    int C = n0 + wn * 32 + q * 8 + (lane & 3) * 2;
                    atomicAdd(&orow[C],     wt * acc[mf][q][hr * 2]);
                    atomicAdd(&orow[C + 1], wt * acc[mf][q][hr * 2 + 1]);
                }
            }
        }
    }
}

// ---------------- launch ----------------
extern "C" void kernel_launch(void* const* d_in, const int* in_sizes, int n_in,
                              void* d_out, int out_size) {
    const float* x   = (const float*)d_in[0];
    const float* gw  = (const float*)d_in[1];
    const float* egw = (const float*)d_in[2];
    const float* euw = (const float*)d_in[3];
    const float* edw = (const float*)d_in[4];
    const float* sgw = (const float*)d_in[5];
    const float* suw = (const float*)d_in[6];
    const float* sdw = (const float*)d_in[7];
    float* out = (float*)d_out;

    cudaFuncSetAttribute(gu_kernel, cudaFuncAttributeMaxDynamicSharedMemorySize, SMEM_TOT);
    cudaFuncSetAttribute(dn_kernel, cudaFuncAttributeMaxDynamicSharedMemorySize, SMEM_TOT);

    int n_out = T_TOK * H_DIM;
    zero_kernel<<<(n_out + 255) / 256, 256>>>(out, n_out);
    routing_kernel<<<T_TOK / 256, 256>>>(x, gw);

    __nv_bfloat16 *p_cx_hi, *p_cx_lo, *p_cgw_hi, *p_cgw_lo, *p_cuw_hi, *p_cuw_lo;
    __nv_bfloat16 *p_cdw_hi, *p_cdw_lo, *p_csg_hi, *p_csg_lo, *p_csu_hi, *p_csu_lo, *p_csd_hi, *p_csd_lo;
    cudaGetSymbolAddress((void**)&p_cx_hi, cx_hi);   cudaGetSymbolAddress((void**)&p_cx_lo, cx_lo);
    cudaGetSymbolAddress((void**)&p_cgw_hi, cgw_hi); cudaGetSymbolAddress((void**)&p_cgw_lo, cgw_lo);
    cudaGetSymbolAddress((void**)&p_cuw_hi, cuw_hi); cudaGetSymbolAddress((void**)&p_cuw_lo, cuw_lo);
    cudaGetSymbolAddress((void**)&p_cdw_hi, cdw_hi); cudaGetSymbolAddress((void**)&p_cdw_lo, cdw_lo);
    cudaGetSymbolAddress((void**)&p_csg_hi, csg_hi); cudaGetSymbolAddress((void**)&p_csg_lo, csg_lo);
    cudaGetSymbolAddress((void**)&p_csu_hi, csu_hi); cudaGetSymbolAddress((void**)&p_csu_lo, csu_lo);
    cudaGetSymbolAddress((void**)&p_csd_hi, csd_hi); cudaGetSymbolAddress((void**)&p_csd_lo, csd_lo);

    cvt_kernel<<<(X_N / 4 + 255) / 256, 256>>>(x, p_cx_hi, p_cx_lo, X_N / 4);
    cvt_kernel<<<(EGW_N / 4 + 255) / 256, 256>>>(egw, p_cgw_hi, p_cgw_lo, EGW_N / 4);
    cvt_kernel<<<(EGW_N / 4 + 255) / 256, 256>>>(euw, p_cuw_hi, p_cuw_lo, EGW_N / 4);
    cvt_kernel<<<(EGW_N / 4 + 255) / 256, 256>>>(edw, p_cdw_hi, p_cdw_lo, EGW_N / 4);
    cvt_kernel<<<(SGW_N / 4 + 255) / 256, 256>>>(sgw, p_csg_hi, p_csg_lo, SGW_N / 4);
    cvt_kernel<<<(SGW_N / 4 + 255) / 256, 256>>>(suw, p_csu_hi, p_csu_lo, SGW_N / 4);
    cvt_kernel<<<(SGW_N / 4 + 255) / 256, 256>>>(sdw, p_csd_hi, p_csd_lo, SGW_N / 4);

    gu_kernel<<<dim3(I_DIM / 64, T_TOK / 128, E_NUM + 1), 512, SMEM_TOT>>>();
    dn_kernel<<<dim3(H_DIM / 128, T_TOK / 128, E_NUM + 1), 512, SMEM_TOT>>>(out);
}